// round 1
// baseline (speedup 1.0000x reference)
#include <cuda_runtime.h>

#define NMAX 50000
#define EMAX 400000
#define ETOTMAX (EMAX + NMAX)
#define ENC_NEG 0x007FFFFFu   // encode(-inf)

// ---------------- scratch (device globals; no allocation allowed) ----------------
__device__ float    g_h1[NMAX * 256];      // layer1 pre-aggregation features
__device__ float    g_agg[NMAX * 256];     // layer1 aggregated -> elu'd features
__device__ float    g_asrc1[NMAX * 2], g_adst1[NMAX * 2];
__device__ float    g_e1[ETOTMAX * 2];     // per-edge logits -> weights
__device__ unsigned g_max1[NMAX * 2];
__device__ float    g_sum1[NMAX * 2];

__device__ float    g_hm[NMAX * 64], g_hl[NMAX * 64];
__device__ float    g_asrc_mu[NMAX], g_adst_mu[NMAX];
__device__ float    g_asrc_ls[NMAX], g_adst_ls[NMAX];
__device__ float    g_emu[ETOTMAX], g_els[ETOTMAX];
__device__ unsigned g_maxmu[NMAX], g_maxls[NMAX];
__device__ float    g_summu[NMAX], g_sumls[NMAX];

// ---------------- helpers ----------------
__device__ __forceinline__ unsigned fenc(float f) {
    int i = __float_as_int(f);
    return (i >= 0) ? ((unsigned)i | 0x80000000u) : ~(unsigned)i;
}
__device__ __forceinline__ float fdec(unsigned u) {
    int i = (u & 0x80000000u) ? (int)(u ^ 0x80000000u) : ~(int)u;
    return __int_as_float(i);
}
__device__ __forceinline__ float lrelu(float v) { return v > 0.f ? v : 0.2f * v; }

__device__ __forceinline__ void red4(float* p, float a, float b, float c, float d) {
    asm volatile("red.global.add.v4.f32 [%0], {%1,%2,%3,%4};"
                 :: "l"(__cvta_generic_to_global(p)), "f"(a), "f"(b), "f"(c), "f"(d)
                 : "memory");
}
__device__ __forceinline__ void red2(float* p, float a, float b) {
    asm volatile("red.global.add.v2.f32 [%0], {%1,%2};"
                 :: "l"(__cvta_generic_to_global(p)), "f"(a), "f"(b)
                 : "memory");
}

// ---------------- init ----------------
__global__ void kinit(int n, float* out) {
    long i = (long)blockIdx.x * blockDim.x + threadIdx.x;
    long na = (long)n * 256;
    if (i < na) g_agg[i] = 0.f;
    if (i < (long)2 * n * 64) out[i] = 0.f;
    if (i < (long)n * 2) { g_sum1[i] = 0.f; g_max1[i] = ENC_NEG; }
    if (i < n) {
        g_summu[i] = 0.f; g_sumls[i] = 0.f;
        g_maxmu[i] = ENC_NEG; g_maxls[i] = ENC_NEG;
    }
}

// ---------------- layer1 GEMM + attention dot-products ----------------
// 256 threads, 8 nodes/block. thread j computes h1[n, j] for 8 nodes.
__global__ void gemm1(const float* __restrict__ x, const float* __restrict__ W1,
                      const float* __restrict__ attS, const float* __restrict__ attD,
                      int n) {
    __shared__ float xs[8 * 128];
    __shared__ float redS[8][8];  // [warp][node]
    __shared__ float redD[8][8];
    const int tid = threadIdx.x;
    const int n0 = blockIdx.x * 8;
    const int nn = min(8, n - n0);

    for (int idx = tid; idx < nn * 128; idx += 256) xs[idx] = x[(long)n0 * 128 + idx];
    __syncthreads();

    const float av_s = attS[tid];  // att flattened [head*128+c] == [j]
    const float av_d = attD[tid];

    float acc[8];
#pragma unroll
    for (int i = 0; i < 8; i++) acc[i] = 0.f;

#pragma unroll 4
    for (int k = 0; k < 128; k += 4) {
        float w0 = W1[(k + 0) * 256 + tid];
        float w1 = W1[(k + 1) * 256 + tid];
        float w2 = W1[(k + 2) * 256 + tid];
        float w3 = W1[(k + 3) * 256 + tid];
#pragma unroll
        for (int i = 0; i < 8; i++) {
            float4 xv = *(const float4*)&xs[i * 128 + k];
            acc[i] += xv.x * w0 + xv.y * w1 + xv.z * w2 + xv.w * w3;
        }
    }

    const int warp = tid >> 5, lane = tid & 31;
    for (int i = 0; i < nn; i++) {
        g_h1[(long)(n0 + i) * 256 + tid] = acc[i];
        float ss = acc[i] * av_s, sd = acc[i] * av_d;
#pragma unroll
        for (int o = 16; o; o >>= 1) {
            ss += __shfl_down_sync(0xFFFFFFFFu, ss, o);
            sd += __shfl_down_sync(0xFFFFFFFFu, sd, o);
        }
        if (lane == 0) { redS[warp][i] = ss; redD[warp][i] = sd; }
    }
    __syncthreads();
    if (tid < 32) {
        int i = tid & 7, h = (tid >> 3) & 1, isD = tid >> 4;
        if (i < nn) {
            float v = 0.f;
#pragma unroll
            for (int w = 0; w < 4; w++) v += isD ? redD[h * 4 + w][i] : redS[h * 4 + w][i];
            if (isD) g_adst1[(n0 + i) * 2 + h] = v;
            else     g_asrc1[(n0 + i) * 2 + h] = v;
        }
    }
}

// ---------------- layer1 edge passes ----------------
__global__ void edgeA1(const int* __restrict__ ei, int E0, int Et) {
    int e = blockIdx.x * blockDim.x + threadIdx.x;
    if (e >= Et) return;
    int s = (e < E0) ? ei[e] : (e - E0);
    int d = (e < E0) ? ei[E0 + e] : (e - E0);
#pragma unroll
    for (int h = 0; h < 2; h++) {
        float v = lrelu(g_asrc1[s * 2 + h] + g_adst1[d * 2 + h]);
        g_e1[e * 2 + h] = v;
        atomicMax(&g_max1[d * 2 + h], fenc(v));
    }
}

__global__ void edgeB1(const int* __restrict__ ei, int E0, int Et) {
    int e = blockIdx.x * blockDim.x + threadIdx.x;
    if (e >= Et) return;
    int d = (e < E0) ? ei[E0 + e] : (e - E0);
#pragma unroll
    for (int h = 0; h < 2; h++) {
        float m = fdec(g_max1[d * 2 + h]);
        float w = __expf(g_e1[e * 2 + h] - m);
        g_e1[e * 2 + h] = w;
        atomicAdd(&g_sum1[d * 2 + h], w);
    }
}

// one warp per edge: 256-float weighted scatter via red.v4
__global__ void scat1(const int* __restrict__ ei, int E0, int Et) {
    int e = (blockIdx.x * blockDim.x + threadIdx.x) >> 5;
    int lane = threadIdx.x & 31;
    if (e >= Et) return;
    int s = (e < E0) ? ei[e] : (e - E0);
    int d = (e < E0) ? ei[E0 + e] : (e - E0);
    float a0 = g_e1[e * 2 + 0] / (g_sum1[d * 2 + 0] + 1e-16f);
    float a1 = g_e1[e * 2 + 1] / (g_sum1[d * 2 + 1] + 1e-16f);
    const float4* hs = (const float4*)(g_h1 + (long)s * 256);
    float* ag = g_agg + (long)d * 256;
    float4 v = hs[lane];
    red4(ag + lane * 4, a0 * v.x, a0 * v.y, a0 * v.z, a0 * v.w);
    v = hs[32 + lane];
    red4(ag + 128 + lane * 4, a1 * v.x, a1 * v.y, a1 * v.z, a1 * v.w);
}

// bias + ELU in place
__global__ void fin1(const float* __restrict__ b1, long total) {
    long i = (long)blockIdx.x * blockDim.x + threadIdx.x;
    if (i >= total) return;
    float v = g_agg[i] + b1[i & 255];
    g_agg[i] = v > 0.f ? v : expm1f(v);
}

// ---------------- layer2 GEMM (mu & ls fused) ----------------
// 128 threads: 0..63 mu channel j, 64..127 ls channel j. 8 nodes/block.
__global__ void gemm2(const float* __restrict__ Wm, const float* __restrict__ Wl,
                      const float* __restrict__ aSm, const float* __restrict__ aDm,
                      const float* __restrict__ aSl, const float* __restrict__ aDl,
                      int n) {
    __shared__ float hs[8 * 256];
    __shared__ float redS[4][8];
    __shared__ float redD[4][8];
    const int tid = threadIdx.x;
    const int n0 = blockIdx.x * 8;
    const int nn = min(8, n - n0);
    const int half = tid >> 6;          // 0 = mu, 1 = ls
    const int j = tid & 63;

    for (int idx = tid; idx < nn * 256; idx += 128) hs[idx] = g_agg[(long)n0 * 256 + idx];
    __syncthreads();

    const float* W = half ? Wl : Wm;
    const float av_s = half ? aSl[j] : aSm[j];
    const float av_d = half ? aDl[j] : aDm[j];

    float acc[8];
#pragma unroll
    for (int i = 0; i < 8; i++) acc[i] = 0.f;

#pragma unroll 4
    for (int k = 0; k < 256; k += 4) {
        float w0 = W[(k + 0) * 64 + j];
        float w1 = W[(k + 1) * 64 + j];
        float w2 = W[(k + 2) * 64 + j];
        float w3 = W[(k + 3) * 64 + j];
#pragma unroll
        for (int i = 0; i < 8; i++) {
            float4 xv = *(const float4*)&hs[i * 256 + k];
            acc[i] += xv.x * w0 + xv.y * w1 + xv.z * w2 + xv.w * w3;
        }
    }

    const int warp = tid >> 5, lane = tid & 31;
    float* dstbuf = half ? g_hl : g_hm;
    for (int i = 0; i < nn; i++) {
        dstbuf[(long)(n0 + i) * 64 + j] = acc[i];
        float ss = acc[i] * av_s, sd = acc[i] * av_d;
#pragma unroll
        for (int o = 16; o; o >>= 1) {
            ss += __shfl_down_sync(0xFFFFFFFFu, ss, o);
            sd += __shfl_down_sync(0xFFFFFFFFu, sd, o);
        }
        if (lane == 0) { redS[warp][i] = ss; redD[warp][i] = sd; }
    }
    __syncthreads();
    if (tid < 32) {
        int i = tid & 7, code = tid >> 3;
        if (i < nn) {
            int node = n0 + i;
            if (code == 0) g_asrc_mu[node] = redS[0][i] + redS[1][i];
            if (code == 1) g_adst_mu[node] = redD[0][i] + redD[1][i];
            if (code == 2) g_asrc_ls[node] = redS[2][i] + redS[3][i];
            if (code == 3) g_adst_ls[node] = redD[2][i] + redD[3][i];
        }
    }
}

// ---------------- layer2 edge passes (mu & ls) ----------------
__global__ void edgeA2(const int* __restrict__ ei, int E0, int Et) {
    int e = blockIdx.x * blockDim.x + threadIdx.x;
    if (e >= Et) return;
    int s = (e < E0) ? ei[e] : (e - E0);
    int d = (e < E0) ? ei[E0 + e] : (e - E0);
    float vm = lrelu(g_asrc_mu[s] + g_adst_mu[d]);
    g_emu[e] = vm;
    atomicMax(&g_maxmu[d], fenc(vm));
    float vl = lrelu(g_asrc_ls[s] + g_adst_ls[d]);
    g_els[e] = vl;
    atomicMax(&g_maxls[d], fenc(vl));
}

__global__ void edgeB2(const int* __restrict__ ei, int E0, int Et) {
    int e = blockIdx.x * blockDim.x + threadIdx.x;
    if (e >= Et) return;
    int d = (e < E0) ? ei[E0 + e] : (e - E0);
    float wm = __expf(g_emu[e] - fdec(g_maxmu[d]));
    g_emu[e] = wm;
    atomicAdd(&g_summu[d], wm);
    float wl = __expf(g_els[e] - fdec(g_maxls[d]));
    g_els[e] = wl;
    atomicAdd(&g_sumls[d], wl);
}

// one warp per edge: 64-float mu + 64-float ls scatter into d_out
__global__ void scat2(const int* __restrict__ ei, int E0, int Et, float* out, int n) {
    int e = (blockIdx.x * blockDim.x + threadIdx.x) >> 5;
    int lane = threadIdx.x & 31;
    if (e >= Et) return;
    int s = (e < E0) ? ei[e] : (e - E0);
    int d = (e < E0) ? ei[E0 + e] : (e - E0);
    float am = g_emu[e] / (g_summu[d] + 1e-16f);
    float al = g_els[e] / (g_sumls[d] + 1e-16f);
    const float2* hm = (const float2*)(g_hm + (long)s * 64);
    const float2* hl = (const float2*)(g_hl + (long)s * 64);
    float2 vm = hm[lane];
    red2(out + (long)d * 64 + lane * 2, am * vm.x, am * vm.y);
    float2 vl = hl[lane];
    red2(out + (long)n * 64 + (long)d * 64 + lane * 2, al * vl.x, al * vl.y);
}

__global__ void finbias(float* out, const float* __restrict__ bm,
                        const float* __restrict__ bl, int n) {
    long i = (long)blockIdx.x * blockDim.x + threadIdx.x;
    long half = (long)n * 64;
    if (i >= 2 * half) return;
    int j = (int)(i & 63);
    out[i] += (i >= half) ? bl[j] : bm[j];
}

// ---------------- launch ----------------
extern "C" void kernel_launch(void* const* d_in, const int* in_sizes, int n_in,
                              void* d_out, int out_size) {
    const float* x     = (const float*)d_in[0];
    const int*   ei    = (const int*)d_in[1];
    const float* W1    = (const float*)d_in[2];
    const float* attS1 = (const float*)d_in[3];
    const float* attD1 = (const float*)d_in[4];
    const float* b1    = (const float*)d_in[5];
    const float* Wm    = (const float*)d_in[6];
    const float* aSm   = (const float*)d_in[7];
    const float* aDm   = (const float*)d_in[8];
    const float* bm    = (const float*)d_in[9];
    const float* Wl    = (const float*)d_in[10];
    const float* aSl   = (const float*)d_in[11];
    const float* aDl   = (const float*)d_in[12];
    const float* bl    = (const float*)d_in[13];
    float* out = (float*)d_out;

    int n  = in_sizes[0] / 128;
    int E0 = in_sizes[1] / 2;
    int Et = E0 + n;

    long initN = (long)n * 256;   // covers all init ranges
    kinit<<<(int)((initN + 255) / 256), 256>>>(n, out);

    gemm1<<<(n + 7) / 8, 256>>>(x, W1, attS1, attD1, n);

    int eb = (Et + 255) / 256;
    edgeA1<<<eb, 256>>>(ei, E0, Et);
    edgeB1<<<eb, 256>>>(ei, E0, Et);
    scat1<<<(int)(((long)Et * 32 + 255) / 256), 256>>>(ei, E0, Et);
    fin1<<<(int)(((long)n * 256 + 255) / 256), 256>>>(b1, (long)n * 256);

    gemm2<<<(n + 7) / 8, 128>>>(Wm, Wl, aSm, aDm, aSl, aDl, n);

    edgeA2<<<eb, 256>>>(ei, E0, Et);
    edgeB2<<<eb, 256>>>(ei, E0, Et);
    scat2<<<(int)(((long)Et * 32 + 255) / 256), 256>>>(ei, E0, Et, out, n);
    finbias<<<(int)(((long)2 * n * 64 + 255) / 256), 256>>>(out, bm, bl, n);
}